// round 13
// baseline (speedup 1.0000x reference)
#include <cuda_runtime.h>
#include <cstdint>

#define BB   8
#define SS   4096
#define HIDD 1024
#define HH   16
#define DHH  64

#define MTA   32                 // k1a rows per tile
#define KC    32                 // k-chunk (floats)
#define NC    (HIDD / KC)        // 32
#define NBLKA (BB * (SS / MTA))  // 1024 k1a blocks

#define MT    128                // k1b rows per tile
#define TILES 32                 // k1b tiles per batch
#define NBLK  (BB * TILES)       // 256 k1b blocks

// ---------- static scratch ----------
__device__ float g_scratch[(size_t)NBLK * HH * HIDD]; // 16.8 MB
__device__ float hbar_scratch[(size_t)NBLK * HIDD];   // 1 MB
__device__ float wqk_eff[2 * HH * HIDD];
__device__ float qs_buf[(size_t)BB * SS * HH];        // 2 MB
__device__ float ks_buf[(size_t)BB * SS * HH];        // 2 MB
__device__ float gsum_buf[BB * HH * HIDD];            // 512 KB
__device__ float hsum_buf[BB * HIDD];                 // 32 KB
__device__ float kv_buf[BB * HH * DHH];
__device__ float mv_buf[BB * HH * DHH];
__device__ float invlen_buf[BB];

typedef unsigned long long u64;

__device__ __forceinline__ u64 ffma2(u64 a, u64 b, u64 c) {
    u64 d;
    asm("fma.rn.f32x2 %0, %1, %2, %3;" : "=l"(d) : "l"(a), "l"(b), "l"(c));
    return d;
}
__device__ __forceinline__ u64 pack2(float x, float y) {
    u64 r; asm("mov.b64 %0, {%1,%2};" : "=l"(r) : "f"(x), "f"(y)); return r;
}
__device__ __forceinline__ float2 unpack2(u64 v) {
    float2 r; asm("mov.b64 {%0,%1}, %2;" : "=f"(r.x), "=f"(r.y) : "l"(v)); return r;
}
__device__ __forceinline__ uint32_t smem_u32(const void* p) {
    uint32_t a;
    asm("{ .reg .u64 t; cvta.to.shared.u64 t, %1; cvt.u32.u64 %0, t; }" : "=r"(a) : "l"(p));
    return a;
}
__device__ __forceinline__ void cp16(uint32_t dst, const void* src) {
    asm volatile("cp.async.ca.shared.global [%0], [%1], 16;" :: "r"(dst), "l"(src) : "memory");
}
__device__ __forceinline__ void cp_commit() {
    asm volatile("cp.async.commit_group;" ::: "memory");
}
__device__ __forceinline__ void cp_wait0() {
    asm volatile("cp.async.wait_group 0;" ::: "memory");
}

// ============================================================
// K0: blocks 0..31 weff ; blocks 32..39 invlen
// ============================================================
__global__ void k0_weff(const float* __restrict__ Wq,
                        const float* __restrict__ Wk,
                        const float* __restrict__ aw,
                        const float* __restrict__ mask) {
    if (blockIdx.x >= 32) {
        int b = blockIdx.x - 32;
        __shared__ float red[256];
        float s = 0.f;
        for (int i = threadIdx.x; i < SS; i += 256) s += mask[(size_t)b * SS + i];
        red[threadIdx.x] = s;
        __syncthreads();
        for (int st = 128; st > 0; st >>= 1) {
            if (threadIdx.x < st) red[threadIdx.x] += red[threadIdx.x + st];
            __syncthreads();
        }
        if (threadIdx.x == 0) invlen_buf[b] = 1.f / red[0];
        return;
    }
    int ch = blockIdx.x >> 4, h = blockIdx.x & 15;
    const float* W = ch ? Wk : Wq;
    __shared__ float a_sh[DHH];
    if (threadIdx.x < DHH) a_sh[threadIdx.x] = aw[h * DHH + threadIdx.x];
    __syncthreads();
    for (int e = threadIdx.x; e < HIDD; e += blockDim.x) {
        float acc = 0.f;
#pragma unroll 8
        for (int d = 0; d < DHH; d++)
            acc += a_sh[d] * W[(size_t)(h * DHH + d) * HIDD + e];
        wqk_eff[(ch * HH + h) * HIDD + e] = acc;
    }
}

// ============================================================
// K1a: GEMM C[32x32] = tile x wqk_eff^T. 128 threads, tile 2x4,
// k-paired FFMA2, 2-stage cp.async (R9 pattern). MTA=32 -> 1024 blocks,
// occ 6: ~7 independent blocks/SM hide all sync/drain bubbles.
// ============================================================
__global__ void __launch_bounds__(128, 6)
k1a_gemm(const float* __restrict__ hidden, const float* __restrict__ mask) {
    __shared__ float As[2][MTA][36];
    __shared__ float Bt[2][32][36];

    const int tile = blockIdx.x;
    const int b = tile >> 7;
    const int s0 = (tile & 127) * MTA;
    const int tid = threadIdx.x;
    const int tx = tid & 7;
    const int ty = tid >> 3;         // 0..15, rows ty, ty+16

    const float* Ab = hidden + ((size_t)b * SS + s0) * HIDD;

    // staging: A = 32 rows x 8 kq units = 256 units; B likewise 256 units
    uint32_t a_dst[2][2], b_dst[2][2];
    const float* a_src[2];
    const float* b_src[2];
#pragma unroll
    for (int i = 0; i < 2; i++) {
        int unit = tid + i * 128;
        int r = unit >> 3, kq = unit & 7;
        a_dst[0][i] = smem_u32(&As[0][r][kq * 4]);
        a_dst[1][i] = smem_u32(&As[1][r][kq * 4]);
        a_src[i] = Ab + (size_t)r * HIDD + kq * 4;
    }
#pragma unroll
    for (int p = 0; p < 2; p++) {
        int unit = tid + p * 128;
        int v = unit >> 3, kq = unit & 7;
        b_dst[0][p] = smem_u32(&Bt[0][v][kq * 4]);
        b_dst[1][p] = smem_u32(&Bt[1][v][kq * 4]);
        b_src[p] = wqk_eff + (size_t)v * HIDD + kq * 4;
    }

    u64 acc[2][4];
#pragma unroll
    for (int i = 0; i < 2; i++)
#pragma unroll
        for (int j = 0; j < 4; j++) acc[i][j] = 0ull;

    // ---- prologue: stage chunk 0 ----
#pragma unroll
    for (int i = 0; i < 2; i++) cp16(a_dst[0][i], a_src[i]);
#pragma unroll
    for (int p = 0; p < 2; p++) cp16(b_dst[0][p], b_src[p]);
    cp_commit();
    cp_wait0();
    __syncthreads();

    // ---- main loop: double-buffered (R9 schedule) ----
#pragma unroll 1
    for (int c = 0; c < NC; c++) {
        const int cur = c & 1, nxt = cur ^ 1;
        if (c + 1 < NC) {
            int k0 = (c + 1) * KC;
#pragma unroll
            for (int i = 0; i < 2; i++) cp16(a_dst[nxt][i], a_src[i] + k0);
#pragma unroll
            for (int p = 0; p < 2; p++) cp16(b_dst[nxt][p], b_src[p] + k0);
            cp_commit();
        }
#pragma unroll
        for (int k = 0; k < KC; k += 2) {
            u64 a[2], bv[4];
#pragma unroll
            for (int i = 0; i < 2; i++) a[i] = *(const u64*)&As[cur][ty + 16 * i][k];
#pragma unroll
            for (int j = 0; j < 4; j++) bv[j] = *(const u64*)&Bt[cur][tx + 8 * j][k];
#pragma unroll
            for (int i = 0; i < 2; i++) {
                acc[i][0] = ffma2(a[i], bv[0], acc[i][0]);
                acc[i][1] = ffma2(a[i], bv[1], acc[i][1]);
                acc[i][2] = ffma2(a[i], bv[2], acc[i][2]);
                acc[i][3] = ffma2(a[i], bv[3], acc[i][3]);
            }
        }
        if (c + 1 < NC) cp_wait0();
        __syncthreads();
    }

    // ---- epilogue: sum k-pair lanes, apply mask, write qs/ks ----
#pragma unroll
    for (int i = 0; i < 2; i++) {
        int row = ty + 16 * i;
        float m = mask[(size_t)b * SS + s0 + row];
        float2 f0 = unpack2(acc[i][0]);
        float2 f1 = unpack2(acc[i][1]);
        float2 f2 = unpack2(acc[i][2]);
        float2 f3 = unpack2(acc[i][3]);
        size_t rb = ((size_t)(b * SS + s0 + row)) * HH;
        qs_buf[rb + tx]     = (f0.x + f0.y) * m;
        qs_buf[rb + tx + 8] = (f1.x + f1.y) * m;
        ks_buf[rb + tx]     = (f2.x + f2.y) * m;
        ks_buf[rb + tx + 8] = (f3.x + f3.y) * m;
    }
}

// ============================================================
// K1b: g[h][e] += ks[s][h]*H[s][e] ; hbar[e] += m[s]*H[s][e]
// (identical to R9)
// ============================================================
__global__ void __launch_bounds__(256, 2)
k1b_accum(const float* __restrict__ hidden, const float* __restrict__ mask) {
    __shared__ u64 ks_dup[MT][16];
    __shared__ u64 m_dup[MT];

    const int tile = blockIdx.x;
    const int b = tile >> 5;
    const int s0 = (tile & 31) * MT;
    const int tid = threadIdx.x;
    const float* Ab = hidden + ((size_t)b * SS + s0) * HIDD;

#pragma unroll
    for (int p = 0; p < 8; p++) {
        int idx = tid + 256 * p;
        int r = idx >> 4, h = idx & 15;
        float v = ks_buf[((size_t)(b * SS + s0 + r)) * HH + h];
        ks_dup[r][h] = pack2(v, v);
    }
    if (tid < MT) {
        float m = mask[(size_t)b * SS + s0 + tid];
        m_dup[tid] = pack2(m, m);
    }
    __syncthreads();

    u64 g[16][2];
#pragma unroll
    for (int h = 0; h < 16; h++) { g[h][0] = 0ull; g[h][1] = 0ull; }
    u64 hb0 = 0ull, hb1 = 0ull;

    const float4* hrow = (const float4*)(Ab + tid * 4);
#pragma unroll 1
    for (int r0 = 0; r0 < MT; r0 += 4) {
        float4 hf[4];
#pragma unroll
        for (int u = 0; u < 4; u++)
            hf[u] = __ldcs(hrow + (size_t)(r0 + u) * (HIDD / 4));
#pragma unroll
        for (int u = 0; u < 4; u++) {
            ulonglong2 hv;
            hv.x = pack2(hf[u].x, hf[u].y);
            hv.y = pack2(hf[u].z, hf[u].w);
            u64 md = m_dup[r0 + u];
            hb0 = ffma2(hv.x, md, hb0);
            hb1 = ffma2(hv.y, md, hb1);
#pragma unroll
            for (int hh = 0; hh < 8; hh++) {
                ulonglong2 kp = *(const ulonglong2*)&ks_dup[r0 + u][hh * 2];
                g[2 * hh + 0][0] = ffma2(hv.x, kp.x, g[2 * hh + 0][0]);
                g[2 * hh + 0][1] = ffma2(hv.y, kp.x, g[2 * hh + 0][1]);
                g[2 * hh + 1][0] = ffma2(hv.x, kp.y, g[2 * hh + 1][0]);
                g[2 * hh + 1][1] = ffma2(hv.y, kp.y, g[2 * hh + 1][1]);
            }
        }
    }

#pragma unroll
    for (int h = 0; h < 16; h++) {
        float2 x = unpack2(g[h][0]), y = unpack2(g[h][1]);
        *(float4*)(g_scratch + ((size_t)tile * HH + h) * HIDD + tid * 4) =
            make_float4(x.x, x.y, y.x, y.y);
    }
    {
        float2 x = unpack2(hb0), y = unpack2(hb1);
        *(float4*)(hbar_scratch + (size_t)tile * HIDD + tid * 4) =
            make_float4(x.x, x.y, y.x, y.y);
    }
}

// ============================================================
// K2r: parallel reduction g_scratch -> gsum_buf, hbar -> hsum_buf
// (identical to R9)
// ============================================================
__global__ void __launch_bounds__(256)
k2r_reduce() {
    int bid = blockIdx.x;
    if (bid < 512) {
        int b = bid >> 6, h = (bid >> 2) & 15, seg = bid & 3;
        int e = seg * 256 + threadIdx.x;
        const float* base = g_scratch + (((size_t)b * TILES) * HH + h) * HIDD + e;
        float a[4];
#pragma unroll
        for (int j = 0; j < 4; j++) a[j] = 0.f;
#pragma unroll
        for (int c = 0; c < TILES; c += 4) {
            float t[4];
#pragma unroll
            for (int j = 0; j < 4; j++) t[j] = base[(size_t)(c + j) * HH * HIDD];
#pragma unroll
            for (int j = 0; j < 4; j++) a[j] += t[j];
        }
        gsum_buf[((b * HH + h) << 10) + e] = (a[0] + a[1]) + (a[2] + a[3]);
    } else {
        int bid2 = bid - 512;
        int b = bid2 >> 2, seg = bid2 & 3;
        int e = seg * 256 + threadIdx.x;
        const float* base = hbar_scratch + ((size_t)b * TILES) * HIDD + e;
        float a[4];
#pragma unroll
        for (int j = 0; j < 4; j++) a[j] = 0.f;
#pragma unroll
        for (int c = 0; c < TILES; c += 4) {
            float t[4];
#pragma unroll
            for (int j = 0; j < 4; j++) t[j] = base[(size_t)(c + j) * HIDD];
#pragma unroll
            for (int j = 0; j < 4; j++) a[j] += t[j];
        }
        hsum_buf[(b << 10) + e] = (a[0] + a[1]) + (a[2] + a[3]);
    }
}

// ============================================================
// K2d: per (b,h): kv/mv = (gsum|hsum) . Wv rows (identical to R9)
// ============================================================
__global__ void __launch_bounds__(256)
k2d_dot(const float* __restrict__ Wv) {
    int b = blockIdx.x >> 4, h = blockIdx.x & 15;
    __shared__ float gsum[HIDD];
    __shared__ float hsum[HIDD];

    {
        int t4 = threadIdx.x * 4;
        *(float4*)&gsum[t4] = *(const float4*)(gsum_buf + ((b * HH + h) << 10) + t4);
        *(float4*)&hsum[t4] = *(const float4*)(hsum_buf + (b << 10) + t4);
    }
    __syncthreads();

    int w = threadIdx.x >> 5, l = threadIdx.x & 31;
#pragma unroll
    for (int dd = 0; dd < 8; dd++) {
        int d = w * 8 + dd;
        const float* wvrow = Wv + (size_t)(h * DHH + d) * HIDD;
        float ak = 0.f, am = 0.f;
#pragma unroll 8
        for (int e2 = l; e2 < HIDD; e2 += 32) {
            float wv = __ldg(wvrow + e2);
            ak += gsum[e2] * wv;
            am += hsum[e2] * wv;
        }
#pragma unroll
        for (int off = 16; off > 0; off >>= 1) {
            ak += __shfl_xor_sync(0xffffffffu, ak, off);
            am += __shfl_xor_sync(0xffffffffu, am, off);
        }
        if (l == 0) {
            kv_buf[((b * HH + h) << 6) + d] = ak;
            mv_buf[((b * HH + h) << 6) + d] = am;
        }
    }
}

// ============================================================
// K3: out = (qs*mv + kv)*invlen (identical to R9)
// ============================================================
__global__ void k3_out(float* __restrict__ out) {
    int row0 = blockIdx.x << 3;
    int b = row0 >> 12;
    int t = threadIdx.x;
    int h = t >> 4;
    int d = (t & 15) << 2;
    float4 mv4 = *(const float4*)(mv_buf + ((b * HH + h) << 6) + d);
    float4 kv4 = *(const float4*)(kv_buf + ((b * HH + h) << 6) + d);
    float il = invlen_buf[b];
    float4 mvi = make_float4(mv4.x * il, mv4.y * il, mv4.z * il, mv4.w * il);
    float4 kvi = make_float4(kv4.x * il, kv4.y * il, kv4.z * il, kv4.w * il);
#pragma unroll
    for (int rr = 0; rr < 8; rr++) {
        int row = row0 + rr;
        float qsv = __ldg(qs_buf + (size_t)row * HH + h);
        float4 o;
        o.x = qsv * mvi.x + kvi.x;
        o.y = qsv * mvi.y + kvi.y;
        o.z = qsv * mvi.z + kvi.z;
        o.w = qsv * mvi.w + kvi.w;
        __stcs(((float4*)out) + (size_t)row * 256 + t, o);
    }
}

// ============================================================
extern "C" void kernel_launch(void* const* d_in, const int* in_sizes, int n_in,
                              void* d_out, int out_size) {
    const float* hidden = (const float*)d_in[0];
    const float* mask   = (const float*)d_in[1];
    const float* Wq     = (const float*)d_in[2];
    const float* Wk     = (const float*)d_in[3];
    const float* Wv     = (const float*)d_in[4];
    const float* aw     = (const float*)d_in[5];
    float* out = (float*)d_out;

    k0_weff<<<40, 256>>>(Wq, Wk, aw, mask);
    k1a_gemm<<<NBLKA, 128>>>(hidden, mask);
    k1b_accum<<<NBLK, 256>>>(hidden, mask);
    k2r_reduce<<<544, 256>>>();
    k2d_dot<<<BB * HH, 256>>>(Wv);
    k3_out<<<BB * SS / 8, 256>>>(out);
}

// round 14
// speedup vs baseline: 1.0913x; 1.0913x over previous
#include <cuda_runtime.h>
#include <cstdint>

#define BB   8
#define SS   4096
#define HIDD 1024
#define HH   16
#define DHH  64

#define MT    128                // rows per tile
#define KC    32                 // k-chunk (floats)
#define NC    (HIDD / KC)        // 32
#define TILES 32
#define NBLK  (BB * TILES)       // 256
#define HALF  (NBLK / 2)         // 128 tiles = batches 0..3

// ---------- static scratch ----------
__device__ float g_scratch[(size_t)NBLK * HH * HIDD]; // 16.8 MB
__device__ float hbar_scratch[(size_t)NBLK * HIDD];   // 1 MB
__device__ float wqk_eff[2 * HH * HIDD];
__device__ float qs_buf[(size_t)BB * SS * HH];        // 2 MB
__device__ float ks_buf[(size_t)BB * SS * HH];        // 2 MB
__device__ float gsum_buf[BB * HH * HIDD];            // 512 KB
__device__ float hsum_buf[BB * HIDD];                 // 32 KB
__device__ float kv_buf[BB * HH * DHH];
__device__ float mv_buf[BB * HH * DHH];
__device__ float invlen_buf[BB];

typedef unsigned long long u64;

__device__ __forceinline__ u64 ffma2(u64 a, u64 b, u64 c) {
    u64 d;
    asm("fma.rn.f32x2 %0, %1, %2, %3;" : "=l"(d) : "l"(a), "l"(b), "l"(c));
    return d;
}
__device__ __forceinline__ u64 pack2(float x, float y) {
    u64 r; asm("mov.b64 %0, {%1,%2};" : "=l"(r) : "f"(x), "f"(y)); return r;
}
__device__ __forceinline__ float2 unpack2(u64 v) {
    float2 r; asm("mov.b64 {%0,%1}, %2;" : "=f"(r.x), "=f"(r.y) : "l"(v)); return r;
}
__device__ __forceinline__ uint32_t smem_u32(const void* p) {
    uint32_t a;
    asm("{ .reg .u64 t; cvta.to.shared.u64 t, %1; cvt.u32.u64 %0, t; }" : "=r"(a) : "l"(p));
    return a;
}
__device__ __forceinline__ void cp16(uint32_t dst, const void* src) {
    asm volatile("cp.async.ca.shared.global [%0], [%1], 16;" :: "r"(dst), "l"(src) : "memory");
}
__device__ __forceinline__ void cp_commit() {
    asm volatile("cp.async.commit_group;" ::: "memory");
}
__device__ __forceinline__ void cp_wait0() {
    asm volatile("cp.async.wait_group 0;" ::: "memory");
}

// ============================================================
// K0: blocks 0..31 weff ; blocks 32..39 invlen
// ============================================================
__global__ void k0_weff(const float* __restrict__ Wq,
                        const float* __restrict__ Wk,
                        const float* __restrict__ aw,
                        const float* __restrict__ mask) {
    if (blockIdx.x >= 32) {
        int b = blockIdx.x - 32;
        __shared__ float red[256];
        float s = 0.f;
        for (int i = threadIdx.x; i < SS; i += 256) s += mask[(size_t)b * SS + i];
        red[threadIdx.x] = s;
        __syncthreads();
        for (int st = 128; st > 0; st >>= 1) {
            if (threadIdx.x < st) red[threadIdx.x] += red[threadIdx.x + st];
            __syncthreads();
        }
        if (threadIdx.x == 0) invlen_buf[b] = 1.f / red[0];
        return;
    }
    int ch = blockIdx.x >> 4, h = blockIdx.x & 15;
    const float* W = ch ? Wk : Wq;
    __shared__ float a_sh[DHH];
    if (threadIdx.x < DHH) a_sh[threadIdx.x] = aw[h * DHH + threadIdx.x];
    __syncthreads();
    for (int e = threadIdx.x; e < HIDD; e += blockDim.x) {
        float acc = 0.f;
#pragma unroll 8
        for (int d = 0; d < DHH; d++)
            acc += a_sh[d] * W[(size_t)(h * DHH + d) * HIDD + e];
        wqk_eff[(ch * HH + h) * HIDD + e] = acc;
    }
}

// ============================================================
// K1a: GEMM C[128x32] = tile x wqk_eff^T. 128 threads, tile 8x4,
// k-paired FFMA2, 2-stage cp.async (R9 — proven optimum). tile0 = offset.
// ============================================================
__global__ void __launch_bounds__(128, 3)
k1a_gemm(const float* __restrict__ hidden, const float* __restrict__ mask, int tile0) {
    __shared__ float As[2][MT][36];
    __shared__ float Bt[2][32][36];

    const int tile = blockIdx.x + tile0;
    const int b = tile >> 5;
    const int s0 = (tile & 31) * MT;
    const int tid = threadIdx.x;
    const int tx = tid & 7;
    const int ty = tid >> 3;

    const float* Ab = hidden + ((size_t)b * SS + s0) * HIDD;

    uint32_t a_dst[2][8], b_dst[2][2];
    const float* a_src[8];
    const float* b_src[2];
#pragma unroll
    for (int i = 0; i < 8; i++) {
        int unit = tid + i * 128;
        int r = unit >> 3, kq = unit & 7;
        a_dst[0][i] = smem_u32(&As[0][r][kq * 4]);
        a_dst[1][i] = smem_u32(&As[1][r][kq * 4]);
        a_src[i] = Ab + (size_t)r * HIDD + kq * 4;
    }
#pragma unroll
    for (int p = 0; p < 2; p++) {
        int unit = tid + p * 128;
        int v = unit >> 3, kq = unit & 7;
        b_dst[0][p] = smem_u32(&Bt[0][v][kq * 4]);
        b_dst[1][p] = smem_u32(&Bt[1][v][kq * 4]);
        b_src[p] = wqk_eff + (size_t)v * HIDD + kq * 4;
    }

    u64 acc[8][4];
#pragma unroll
    for (int i = 0; i < 8; i++)
#pragma unroll
        for (int j = 0; j < 4; j++) acc[i][j] = 0ull;

#pragma unroll
    for (int i = 0; i < 8; i++) cp16(a_dst[0][i], a_src[i]);
#pragma unroll
    for (int p = 0; p < 2; p++) cp16(b_dst[0][p], b_src[p]);
    cp_commit();
    cp_wait0();
    __syncthreads();

#pragma unroll 1
    for (int c = 0; c < NC; c++) {
        const int cur = c & 1, nxt = cur ^ 1;
        if (c + 1 < NC) {
            int k0 = (c + 1) * KC;
#pragma unroll
            for (int i = 0; i < 8; i++) cp16(a_dst[nxt][i], a_src[i] + k0);
#pragma unroll
            for (int p = 0; p < 2; p++) cp16(b_dst[nxt][p], b_src[p] + k0);
            cp_commit();
        }
#pragma unroll
        for (int k = 0; k < KC; k += 2) {
            u64 a[8], bv[4];
#pragma unroll
            for (int i = 0; i < 8; i++) a[i] = *(const u64*)&As[cur][ty + 16 * i][k];
#pragma unroll
            for (int j = 0; j < 4; j++) bv[j] = *(const u64*)&Bt[cur][tx + 8 * j][k];
#pragma unroll
            for (int i = 0; i < 8; i++) {
                acc[i][0] = ffma2(a[i], bv[0], acc[i][0]);
                acc[i][1] = ffma2(a[i], bv[1], acc[i][1]);
                acc[i][2] = ffma2(a[i], bv[2], acc[i][2]);
                acc[i][3] = ffma2(a[i], bv[3], acc[i][3]);
            }
        }
        if (c + 1 < NC) cp_wait0();
        __syncthreads();
    }

#pragma unroll
    for (int i = 0; i < 8; i++) {
        int row = ty + 16 * i;
        float m = mask[(size_t)b * SS + s0 + row];
        float2 f0 = unpack2(acc[i][0]);
        float2 f1 = unpack2(acc[i][1]);
        float2 f2 = unpack2(acc[i][2]);
        float2 f3 = unpack2(acc[i][3]);
        size_t rb = ((size_t)(b * SS + s0 + row)) * HH;
        qs_buf[rb + tx]     = (f0.x + f0.y) * m;
        qs_buf[rb + tx + 8] = (f1.x + f1.y) * m;
        ks_buf[rb + tx]     = (f2.x + f2.y) * m;
        ks_buf[rb + tx + 8] = (f3.x + f3.y) * m;
    }
}

// ============================================================
// K1b: g[h][e] += ks[s][h]*H[s][e] ; hbar[e] += m[s]*H[s][e]  (R9)
// ============================================================
__global__ void __launch_bounds__(256, 2)
k1b_accum(const float* __restrict__ hidden, const float* __restrict__ mask, int tile0) {
    __shared__ u64 ks_dup[MT][16];
    __shared__ u64 m_dup[MT];

    const int tile = blockIdx.x + tile0;
    const int b = tile >> 5;
    const int s0 = (tile & 31) * MT;
    const int tid = threadIdx.x;
    const float* Ab = hidden + ((size_t)b * SS + s0) * HIDD;

#pragma unroll
    for (int p = 0; p < 8; p++) {
        int idx = tid + 256 * p;
        int r = idx >> 4, h = idx & 15;
        float v = ks_buf[((size_t)(b * SS + s0 + r)) * HH + h];
        ks_dup[r][h] = pack2(v, v);
    }
    if (tid < MT) {
        float m = mask[(size_t)b * SS + s0 + tid];
        m_dup[tid] = pack2(m, m);
    }
    __syncthreads();

    u64 g[16][2];
#pragma unroll
    for (int h = 0; h < 16; h++) { g[h][0] = 0ull; g[h][1] = 0ull; }
    u64 hb0 = 0ull, hb1 = 0ull;

    const float4* hrow = (const float4*)(Ab + tid * 4);
#pragma unroll 1
    for (int r0 = 0; r0 < MT; r0 += 4) {
        float4 hf[4];
#pragma unroll
        for (int u = 0; u < 4; u++)
            hf[u] = __ldcs(hrow + (size_t)(r0 + u) * (HIDD / 4));
#pragma unroll
        for (int u = 0; u < 4; u++) {
            ulonglong2 hv;
            hv.x = pack2(hf[u].x, hf[u].y);
            hv.y = pack2(hf[u].z, hf[u].w);
            u64 md = m_dup[r0 + u];
            hb0 = ffma2(hv.x, md, hb0);
            hb1 = ffma2(hv.y, md, hb1);
#pragma unroll
            for (int hh = 0; hh < 8; hh++) {
                ulonglong2 kp = *(const ulonglong2*)&ks_dup[r0 + u][hh * 2];
                g[2 * hh + 0][0] = ffma2(hv.x, kp.x, g[2 * hh + 0][0]);
                g[2 * hh + 0][1] = ffma2(hv.y, kp.x, g[2 * hh + 0][1]);
                g[2 * hh + 1][0] = ffma2(hv.x, kp.y, g[2 * hh + 1][0]);
                g[2 * hh + 1][1] = ffma2(hv.y, kp.y, g[2 * hh + 1][1]);
            }
        }
    }

#pragma unroll
    for (int h = 0; h < 16; h++) {
        float2 x = unpack2(g[h][0]), y = unpack2(g[h][1]);
        *(float4*)(g_scratch + ((size_t)tile * HH + h) * HIDD + tid * 4) =
            make_float4(x.x, x.y, y.x, y.y);
    }
    {
        float2 x = unpack2(hb0), y = unpack2(hb1);
        *(float4*)(hbar_scratch + (size_t)tile * HIDD + tid * 4) =
            make_float4(x.x, x.y, y.x, y.y);
    }
}

// ============================================================
// K2r: parallel reduction g_scratch -> gsum_buf, hbar -> hsum_buf (R9)
// ============================================================
__global__ void __launch_bounds__(256)
k2r_reduce() {
    int bid = blockIdx.x;
    if (bid < 512) {
        int b = bid >> 6, h = (bid >> 2) & 15, seg = bid & 3;
        int e = seg * 256 + threadIdx.x;
        const float* base = g_scratch + (((size_t)b * TILES) * HH + h) * HIDD + e;
        float a[4];
#pragma unroll
        for (int j = 0; j < 4; j++) a[j] = 0.f;
#pragma unroll
        for (int c = 0; c < TILES; c += 4) {
            float t[4];
#pragma unroll
            for (int j = 0; j < 4; j++) t[j] = base[(size_t)(c + j) * HH * HIDD];
#pragma unroll
            for (int j = 0; j < 4; j++) a[j] += t[j];
        }
        gsum_buf[((b * HH + h) << 10) + e] = (a[0] + a[1]) + (a[2] + a[3]);
    } else {
        int bid2 = bid - 512;
        int b = bid2 >> 2, seg = bid2 & 3;
        int e = seg * 256 + threadIdx.x;
        const float* base = hbar_scratch + ((size_t)b * TILES) * HIDD + e;
        float a[4];
#pragma unroll
        for (int j = 0; j < 4; j++) a[j] = 0.f;
#pragma unroll
        for (int c = 0; c < TILES; c += 4) {
            float t[4];
#pragma unroll
            for (int j = 0; j < 4; j++) t[j] = base[(size_t)(c + j) * HIDD];
#pragma unroll
            for (int j = 0; j < 4; j++) a[j] += t[j];
        }
        hsum_buf[(b << 10) + e] = (a[0] + a[1]) + (a[2] + a[3]);
    }
}

// ============================================================
// K2d: per (b,h): kv/mv = (gsum|hsum) . Wv rows (R9)
// ============================================================
__global__ void __launch_bounds__(256)
k2d_dot(const float* __restrict__ Wv) {
    int b = blockIdx.x >> 4, h = blockIdx.x & 15;
    __shared__ float gsum[HIDD];
    __shared__ float hsum[HIDD];

    {
        int t4 = threadIdx.x * 4;
        *(float4*)&gsum[t4] = *(const float4*)(gsum_buf + ((b * HH + h) << 10) + t4);
        *(float4*)&hsum[t4] = *(const float4*)(hsum_buf + (b << 10) + t4);
    }
    __syncthreads();

    int w = threadIdx.x >> 5, l = threadIdx.x & 31;
#pragma unroll
    for (int dd = 0; dd < 8; dd++) {
        int d = w * 8 + dd;
        const float* wvrow = Wv + (size_t)(h * DHH + d) * HIDD;
        float ak = 0.f, am = 0.f;
#pragma unroll 8
        for (int e2 = l; e2 < HIDD; e2 += 32) {
            float wv = __ldg(wvrow + e2);
            ak += gsum[e2] * wv;
            am += hsum[e2] * wv;
        }
#pragma unroll
        for (int off = 16; off > 0; off >>= 1) {
            ak += __shfl_xor_sync(0xffffffffu, ak, off);
            am += __shfl_xor_sync(0xffffffffu, am, off);
        }
        if (l == 0) {
            kv_buf[((b * HH + h) << 6) + d] = ak;
            mv_buf[((b * HH + h) << 6) + d] = am;
        }
    }
}

// ============================================================
// K3: out = (qs*mv + kv)*invlen (R9)
// ============================================================
__global__ void k3_out(float* __restrict__ out) {
    int row0 = blockIdx.x << 3;
    int b = row0 >> 12;
    int t = threadIdx.x;
    int h = t >> 4;
    int d = (t & 15) << 2;
    float4 mv4 = *(const float4*)(mv_buf + ((b * HH + h) << 6) + d);
    float4 kv4 = *(const float4*)(kv_buf + ((b * HH + h) << 6) + d);
    float il = invlen_buf[b];
    float4 mvi = make_float4(mv4.x * il, mv4.y * il, mv4.z * il, mv4.w * il);
    float4 kvi = make_float4(kv4.x * il, kv4.y * il, kv4.z * il, kv4.w * il);
#pragma unroll
    for (int rr = 0; rr < 8; rr++) {
        int row = row0 + rr;
        float qsv = __ldg(qs_buf + (size_t)row * HH + h);
        float4 o;
        o.x = qsv * mvi.x + kvi.x;
        o.y = qsv * mvi.y + kvi.y;
        o.z = qsv * mvi.z + kvi.z;
        o.w = qsv * mvi.w + kvi.w;
        __stcs(((float4*)out) + (size_t)row * 256 + t, o);
    }
}

// ============================================================
// Launch: fork-join — k1b(lo) on stream s2 overlaps k1a(hi) on the
// default stream. Streams/events created fresh per call (capture-legal,
// no device allocations, no static state).
// ============================================================
extern "C" void kernel_launch(void* const* d_in, const int* in_sizes, int n_in,
                              void* d_out, int out_size) {
    const float* hidden = (const float*)d_in[0];
    const float* mask   = (const float*)d_in[1];
    const float* Wq     = (const float*)d_in[2];
    const float* Wk     = (const float*)d_in[3];
    const float* Wv     = (const float*)d_in[4];
    const float* aw     = (const float*)d_in[5];
    float* out = (float*)d_out;

    cudaStream_t s2;
    cudaEvent_t e1, e3;
    cudaStreamCreateWithFlags(&s2, cudaStreamNonBlocking);
    cudaEventCreateWithFlags(&e1, cudaEventDisableTiming);
    cudaEventCreateWithFlags(&e3, cudaEventDisableTiming);

    k0_weff<<<40, 256>>>(Wq, Wk, aw, mask);

    // k1a lower half (batches 0..3), then fork
    k1a_gemm<<<HALF, 128>>>(hidden, mask, 0);
    cudaEventRecord(e1, 0);

    // default stream: k1a upper half
    k1a_gemm<<<HALF, 128>>>(hidden, mask, HALF);

    // s2: k1b lower half, concurrent with k1a upper half
    cudaStreamWaitEvent(s2, e1, 0);
    k1b_accum<<<HALF, 256, 0, s2>>>(hidden, mask, 0);
    cudaEventRecord(e3, s2);

    // default stream: k1b upper half, then join s2
    k1b_accum<<<HALF, 256>>>(hidden, mask, HALF);
    cudaStreamWaitEvent(0, e3, 0);

    k2r_reduce<<<544, 256>>>();
    k2d_dot<<<BB * HH, 256>>>(Wv);
    k3_out<<<BB * SS / 8, 256>>>(out);
}

// round 15
// speedup vs baseline: 1.1619x; 1.0647x over previous
#include <cuda_runtime.h>
#include <cstdint>

#define BB   8
#define SS   4096
#define HIDD 1024
#define HH   16
#define DHH  64

#define MT    128                // rows per tile
#define KC    32                 // k-chunk (floats)
#define NC    (HIDD / KC)        // 32
#define TILES 32
#define NBLK  (BB * TILES)       // 256

// ---------- static scratch ----------
__device__ float g_scratch[(size_t)NBLK * HH * HIDD]; // 16.8 MB
__device__ float hbar_scratch[(size_t)NBLK * HIDD];   // 1 MB
__device__ float wqk_eff[2 * HH * HIDD];
__device__ float qs_buf[(size_t)BB * SS * HH];        // 2 MB
__device__ float ks_buf[(size_t)BB * SS * HH];        // 2 MB
__device__ float gsum_buf[BB * HH * HIDD];            // 512 KB
__device__ float hsum_buf[BB * HIDD];                 // 32 KB
__device__ float kv_buf[BB * HH * DHH];
__device__ float mv_buf[BB * HH * DHH];
__device__ float invlen_buf[BB];

typedef unsigned long long u64;

__device__ __forceinline__ u64 ffma2(u64 a, u64 b, u64 c) {
    u64 d;
    asm("fma.rn.f32x2 %0, %1, %2, %3;" : "=l"(d) : "l"(a), "l"(b), "l"(c));
    return d;
}
__device__ __forceinline__ u64 pack2(float x, float y) {
    u64 r; asm("mov.b64 %0, {%1,%2};" : "=l"(r) : "f"(x), "f"(y)); return r;
}
__device__ __forceinline__ float2 unpack2(u64 v) {
    float2 r; asm("mov.b64 {%0,%1}, %2;" : "=f"(r.x), "=f"(r.y) : "l"(v)); return r;
}
__device__ __forceinline__ uint32_t smem_u32(const void* p) {
    uint32_t a;
    asm("{ .reg .u64 t; cvta.to.shared.u64 t, %1; cvt.u32.u64 %0, t; }" : "=r"(a) : "l"(p));
    return a;
}
__device__ __forceinline__ void cp16(uint32_t dst, const void* src) {
    asm volatile("cp.async.ca.shared.global [%0], [%1], 16;" :: "r"(dst), "l"(src) : "memory");
}
__device__ __forceinline__ void cp_commit() {
    asm volatile("cp.async.commit_group;" ::: "memory");
}
__device__ __forceinline__ void cp_wait0() {
    asm volatile("cp.async.wait_group 0;" ::: "memory");
}

// ============================================================
// K0: blocks 0..31 weff ; blocks 32..39 invlen
// ============================================================
__global__ void k0_weff(const float* __restrict__ Wq,
                        const float* __restrict__ Wk,
                        const float* __restrict__ aw,
                        const float* __restrict__ mask) {
    if (blockIdx.x >= 32) {
        int b = blockIdx.x - 32;
        __shared__ float red[256];
        float s = 0.f;
        for (int i = threadIdx.x; i < SS; i += 256) s += mask[(size_t)b * SS + i];
        red[threadIdx.x] = s;
        __syncthreads();
        for (int st = 128; st > 0; st >>= 1) {
            if (threadIdx.x < st) red[threadIdx.x] += red[threadIdx.x + st];
            __syncthreads();
        }
        if (threadIdx.x == 0) invlen_buf[b] = 1.f / red[0];
        return;
    }
    int ch = blockIdx.x >> 4, h = blockIdx.x & 15;
    const float* W = ch ? Wk : Wq;
    __shared__ float a_sh[DHH];
    if (threadIdx.x < DHH) a_sh[threadIdx.x] = aw[h * DHH + threadIdx.x];
    __syncthreads();
    for (int e = threadIdx.x; e < HIDD; e += blockDim.x) {
        float acc = 0.f;
#pragma unroll 8
        for (int d = 0; d < DHH; d++)
            acc += a_sh[d] * W[(size_t)(h * DHH + d) * HIDD + e];
        wqk_eff[(ch * HH + h) * HIDD + e] = acc;
    }
}

// ============================================================
// K1a: GEMM C[128x32] = tile x wqk_eff^T. 128 threads, tile 8x4,
// k-paired FFMA2, 2-stage cp.async (R9 — proven optimum).
// ============================================================
__global__ void __launch_bounds__(128, 3)
k1a_gemm(const float* __restrict__ hidden, const float* __restrict__ mask) {
    __shared__ float As[2][MT][36];
    __shared__ float Bt[2][32][36];

    const int tile = blockIdx.x;
    const int b = tile >> 5;
    const int s0 = (tile & 31) * MT;
    const int tid = threadIdx.x;
    const int tx = tid & 7;
    const int ty = tid >> 3;

    const float* Ab = hidden + ((size_t)b * SS + s0) * HIDD;

    uint32_t a_dst[2][8], b_dst[2][2];
    const float* a_src[8];
    const float* b_src[2];
#pragma unroll
    for (int i = 0; i < 8; i++) {
        int unit = tid + i * 128;
        int r = unit >> 3, kq = unit & 7;
        a_dst[0][i] = smem_u32(&As[0][r][kq * 4]);
        a_dst[1][i] = smem_u32(&As[1][r][kq * 4]);
        a_src[i] = Ab + (size_t)r * HIDD + kq * 4;
    }
#pragma unroll
    for (int p = 0; p < 2; p++) {
        int unit = tid + p * 128;
        int v = unit >> 3, kq = unit & 7;
        b_dst[0][p] = smem_u32(&Bt[0][v][kq * 4]);
        b_dst[1][p] = smem_u32(&Bt[1][v][kq * 4]);
        b_src[p] = wqk_eff + (size_t)v * HIDD + kq * 4;
    }

    u64 acc[8][4];
#pragma unroll
    for (int i = 0; i < 8; i++)
#pragma unroll
        for (int j = 0; j < 4; j++) acc[i][j] = 0ull;

#pragma unroll
    for (int i = 0; i < 8; i++) cp16(a_dst[0][i], a_src[i]);
#pragma unroll
    for (int p = 0; p < 2; p++) cp16(b_dst[0][p], b_src[p]);
    cp_commit();
    cp_wait0();
    __syncthreads();

#pragma unroll 1
    for (int c = 0; c < NC; c++) {
        const int cur = c & 1, nxt = cur ^ 1;
        if (c + 1 < NC) {
            int k0 = (c + 1) * KC;
#pragma unroll
            for (int i = 0; i < 8; i++) cp16(a_dst[nxt][i], a_src[i] + k0);
#pragma unroll
            for (int p = 0; p < 2; p++) cp16(b_dst[nxt][p], b_src[p] + k0);
            cp_commit();
        }
#pragma unroll
        for (int k = 0; k < KC; k += 2) {
            u64 a[8], bv[4];
#pragma unroll
            for (int i = 0; i < 8; i++) a[i] = *(const u64*)&As[cur][ty + 16 * i][k];
#pragma unroll
            for (int j = 0; j < 4; j++) bv[j] = *(const u64*)&Bt[cur][tx + 8 * j][k];
#pragma unroll
            for (int i = 0; i < 8; i++) {
                acc[i][0] = ffma2(a[i], bv[0], acc[i][0]);
                acc[i][1] = ffma2(a[i], bv[1], acc[i][1]);
                acc[i][2] = ffma2(a[i], bv[2], acc[i][2]);
                acc[i][3] = ffma2(a[i], bv[3], acc[i][3]);
            }
        }
        if (c + 1 < NC) cp_wait0();
        __syncthreads();
    }

#pragma unroll
    for (int i = 0; i < 8; i++) {
        int row = ty + 16 * i;
        float m = mask[(size_t)b * SS + s0 + row];
        float2 f0 = unpack2(acc[i][0]);
        float2 f1 = unpack2(acc[i][1]);
        float2 f2 = unpack2(acc[i][2]);
        float2 f3 = unpack2(acc[i][3]);
        size_t rb = ((size_t)(b * SS + s0 + row)) * HH;
        qs_buf[rb + tx]     = (f0.x + f0.y) * m;
        qs_buf[rb + tx + 8] = (f1.x + f1.y) * m;
        ks_buf[rb + tx]     = (f2.x + f2.y) * m;
        ks_buf[rb + tx + 8] = (f3.x + f3.y) * m;
    }
}

// ============================================================
// K1b: g[h][e] += ks[s][h]*H[s][e] ; hbar[e] += m[s]*H[s][e]
// REVERSED tile order: block 0 processes the tile k1a touched last,
// harvesting L2-resident hidden data (126 MB L2 vs 134 MB tensor).
// ============================================================
__global__ void __launch_bounds__(256, 2)
k1b_accum(const float* __restrict__ hidden, const float* __restrict__ mask) {
    __shared__ u64 ks_dup[MT][16];
    __shared__ u64 m_dup[MT];

    const int tile = (NBLK - 1) - blockIdx.x;   // reverse traversal
    const int b = tile >> 5;
    const int s0 = (tile & 31) * MT;
    const int tid = threadIdx.x;
    const float* Ab = hidden + ((size_t)b * SS + s0) * HIDD;

#pragma unroll
    for (int p = 0; p < 8; p++) {
        int idx = tid + 256 * p;
        int r = idx >> 4, h = idx & 15;
        float v = ks_buf[((size_t)(b * SS + s0 + r)) * HH + h];
        ks_dup[r][h] = pack2(v, v);
    }
    if (tid < MT) {
        float m = mask[(size_t)b * SS + s0 + tid];
        m_dup[tid] = pack2(m, m);
    }
    __syncthreads();

    u64 g[16][2];
#pragma unroll
    for (int h = 0; h < 16; h++) { g[h][0] = 0ull; g[h][1] = 0ull; }
    u64 hb0 = 0ull, hb1 = 0ull;

    const float4* hrow = (const float4*)(Ab + tid * 4);
#pragma unroll 1
    for (int r0 = 0; r0 < MT; r0 += 4) {
        float4 hf[4];
#pragma unroll
        for (int u = 0; u < 4; u++)
            hf[u] = __ldcs(hrow + (size_t)(r0 + u) * (HIDD / 4));
#pragma unroll
        for (int u = 0; u < 4; u++) {
            ulonglong2 hv;
            hv.x = pack2(hf[u].x, hf[u].y);
            hv.y = pack2(hf[u].z, hf[u].w);
            u64 md = m_dup[r0 + u];
            hb0 = ffma2(hv.x, md, hb0);
            hb1 = ffma2(hv.y, md, hb1);
#pragma unroll
            for (int hh = 0; hh < 8; hh++) {
                ulonglong2 kp = *(const ulonglong2*)&ks_dup[r0 + u][hh * 2];
                g[2 * hh + 0][0] = ffma2(hv.x, kp.x, g[2 * hh + 0][0]);
                g[2 * hh + 0][1] = ffma2(hv.y, kp.x, g[2 * hh + 0][1]);
                g[2 * hh + 1][0] = ffma2(hv.x, kp.y, g[2 * hh + 1][0]);
                g[2 * hh + 1][1] = ffma2(hv.y, kp.y, g[2 * hh + 1][1]);
            }
        }
    }

#pragma unroll
    for (int h = 0; h < 16; h++) {
        float2 x = unpack2(g[h][0]), y = unpack2(g[h][1]);
        *(float4*)(g_scratch + ((size_t)tile * HH + h) * HIDD + tid * 4) =
            make_float4(x.x, x.y, y.x, y.y);
    }
    {
        float2 x = unpack2(hb0), y = unpack2(hb1);
        *(float4*)(hbar_scratch + (size_t)tile * HIDD + tid * 4) =
            make_float4(x.x, x.y, y.x, y.y);
    }
}

// ============================================================
// K2r: parallel reduction g_scratch -> gsum_buf, hbar -> hsum_buf (R9)
// ============================================================
__global__ void __launch_bounds__(256)
k2r_reduce() {
    int bid = blockIdx.x;
    if (bid < 512) {
        int b = bid >> 6, h = (bid >> 2) & 15, seg = bid & 3;
        int e = seg * 256 + threadIdx.x;
        const float* base = g_scratch + (((size_t)b * TILES) * HH + h) * HIDD + e;
        float a[4];
#pragma unroll
        for (int j = 0; j < 4; j++) a[j] = 0.f;
#pragma unroll
        for (int c = 0; c < TILES; c += 4) {
            float t[4];
#pragma unroll
            for (int j = 0; j < 4; j++) t[j] = base[(size_t)(c + j) * HH * HIDD];
#pragma unroll
            for (int j = 0; j < 4; j++) a[j] += t[j];
        }
        gsum_buf[((b * HH + h) << 10) + e] = (a[0] + a[1]) + (a[2] + a[3]);
    } else {
        int bid2 = bid - 512;
        int b = bid2 >> 2, seg = bid2 & 3;
        int e = seg * 256 + threadIdx.x;
        const float* base = hbar_scratch + ((size_t)b * TILES) * HIDD + e;
        float a[4];
#pragma unroll
        for (int j = 0; j < 4; j++) a[j] = 0.f;
#pragma unroll
        for (int c = 0; c < TILES; c += 4) {
            float t[4];
#pragma unroll
            for (int j = 0; j < 4; j++) t[j] = base[(size_t)(c + j) * HIDD];
#pragma unroll
            for (int j = 0; j < 4; j++) a[j] += t[j];
        }
        hsum_buf[(b << 10) + e] = (a[0] + a[1]) + (a[2] + a[3]);
    }
}

// ============================================================
// K2d: per (b,h): kv/mv = (gsum|hsum) . Wv rows (R9)
// ============================================================
__global__ void __launch_bounds__(256)
k2d_dot(const float* __restrict__ Wv) {
    int b = blockIdx.x >> 4, h = blockIdx.x & 15;
    __shared__ float gsum[HIDD];
    __shared__ float hsum[HIDD];

    {
        int t4 = threadIdx.x * 4;
        *(float4*)&gsum[t4] = *(const float4*)(gsum_buf + ((b * HH + h) << 10) + t4);
        *(float4*)&hsum[t4] = *(const float4*)(hsum_buf + (b << 10) + t4);
    }
    __syncthreads();

    int w = threadIdx.x >> 5, l = threadIdx.x & 31;
#pragma unroll
    for (int dd = 0; dd < 8; dd++) {
        int d = w * 8 + dd;
        const float* wvrow = Wv + (size_t)(h * DHH + d) * HIDD;
        float ak = 0.f, am = 0.f;
#pragma unroll 8
        for (int e2 = l; e2 < HIDD; e2 += 32) {
            float wv = __ldg(wvrow + e2);
            ak += gsum[e2] * wv;
            am += hsum[e2] * wv;
        }
#pragma unroll
        for (int off = 16; off > 0; off >>= 1) {
            ak += __shfl_xor_sync(0xffffffffu, ak, off);
            am += __shfl_xor_sync(0xffffffffu, am, off);
        }
        if (l == 0) {
            kv_buf[((b * HH + h) << 6) + d] = ak;
            mv_buf[((b * HH + h) << 6) + d] = am;
        }
    }
}

// ============================================================
// K3: out = (qs*mv + kv)*invlen (R9)
// ============================================================
__global__ void k3_out(float* __restrict__ out) {
    int row0 = blockIdx.x << 3;
    int b = row0 >> 12;
    int t = threadIdx.x;
    int h = t >> 4;
    int d = (t & 15) << 2;
    float4 mv4 = *(const float4*)(mv_buf + ((b * HH + h) << 6) + d);
    float4 kv4 = *(const float4*)(kv_buf + ((b * HH + h) << 6) + d);
    float il = invlen_buf[b];
    float4 mvi = make_float4(mv4.x * il, mv4.y * il, mv4.z * il, mv4.w * il);
    float4 kvi = make_float4(kv4.x * il, kv4.y * il, kv4.z * il, kv4.w * il);
#pragma unroll
    for (int rr = 0; rr < 8; rr++) {
        int row = row0 + rr;
        float qsv = __ldg(qs_buf + (size_t)row * HH + h);
        float4 o;
        o.x = qsv * mvi.x + kvi.x;
        o.y = qsv * mvi.y + kvi.y;
        o.z = qsv * mvi.z + kvi.z;
        o.w = qsv * mvi.w + kvi.w;
        __stcs(((float4*)out) + (size_t)row * 256 + t, o);
    }
}

// ============================================================
extern "C" void kernel_launch(void* const* d_in, const int* in_sizes, int n_in,
                              void* d_out, int out_size) {
    const float* hidden = (const float*)d_in[0];
    const float* mask   = (const float*)d_in[1];
    const float* Wq     = (const float*)d_in[2];
    const float* Wk     = (const float*)d_in[3];
    const float* Wv     = (const float*)d_in[4];
    const float* aw     = (const float*)d_in[5];
    float* out = (float*)d_out;

    k0_weff<<<40, 256>>>(Wq, Wk, aw, mask);
    k1a_gemm<<<NBLK, 128>>>(hidden, mask);
    k1b_accum<<<NBLK, 256>>>(hidden, mask);
    k2r_reduce<<<544, 256>>>();
    k2d_dot<<<BB * HH, 256>>>(Wv);
    k3_out<<<BB * SS / 8, 256>>>(out);
}